// round 16
// baseline (speedup 1.0000x reference)
#include <cuda_runtime.h>
#include <cuda_bf16.h>

// Problem constants
#define BB 8
#define NN 512
#define DD 64
#define EE 32

#define JT 128                // edge: j's per block (8 warps x 16 j)
#define JR 8                  // edge: j's per thread
#define SS 16                 // i-splits
#define IT (NN / SS)          // 32 i-rows per block

#define RPB 16                // proj: x-rows per block
#define RPW 4                 // proj: rows per warp

// Scratch (allocation-free rule -> __device__ globals)
__device__ float g_src [BB * NN * EE];        // src[b,n,e]
__device__ float g_dstb[BB * NN * EE];        // dst[b,n,e] + be[e]

// ---- packed fp32 pair helpers (sm_103a FADD2/FFMA2 via PTX f32x2) ----------
union F2U { unsigned long long u; float2 f; };

__device__ __forceinline__ unsigned long long add2(unsigned long long a,
                                                   unsigned long long b) {
    unsigned long long r;
    asm("add.rn.f32x2 %0, %1, %2;" : "=l"(r) : "l"(a), "l"(b));
    return r;
}
__device__ __forceinline__ unsigned long long fma2(unsigned long long a,
                                                   unsigned long long b,
                                                   unsigned long long c) {
    unsigned long long r;
    asm("fma.rn.f32x2 %0, %1, %2, %3;" : "=l"(r) : "l"(a), "l"(b), "l"(c));
    return r;
}

// ---------------------------------------------------------------------------
// Kernel 1 (R14 exact): src = x @ We[:D], dstb = x @ We[D:] + be
// Blocks 0..15 also initialize out[] = br (stream order protects this).
// ---------------------------------------------------------------------------
__global__ __launch_bounds__(256) void proj_kernel(
    const float* __restrict__ x,
    const float* __restrict__ We,
    const float* __restrict__ be,
    const float* __restrict__ br,
    float* __restrict__ out)
{
    const int row0 = blockIdx.x * RPB;
    __shared__ float xs [RPB][DD];              // 4 KB
    __shared__ float Wsh[2 * DD][EE];           // 16 KB

    const int tid = threadIdx.x;

    if (blockIdx.x < 16)                        // out init: 16*256 = 4096
        out[blockIdx.x * 256 + tid] = br[0];

    #pragma unroll
    for (int k = 0; k < 4; k++)
        ((float4*)Wsh)[k * 256 + tid] = ((const float4*)We)[k * 256 + tid];
    ((float4*)xs)[tid] = ((const float4*)(x + row0 * DD))[tid];
    __syncthreads();

    const int lane = tid & 31;                  // = e
    const int w    = tid >> 5;
    const int half = w >> 2;                    // 0 = src, 1 = dst
    const int r0   = (w & 3) * RPW;

    const float* Wh = &Wsh[half * DD][0];
    const float bias = half ? be[lane] : 0.0f;

    float acc[RPW];
    #pragma unroll
    for (int r = 0; r < RPW; r++) acc[r] = bias;

    #pragma unroll
    for (int d4 = 0; d4 < DD; d4 += 4) {
        float4 xv[RPW];
        #pragma unroll
        for (int r = 0; r < RPW; r++)
            xv[r] = *(const float4*)&xs[r0 + r][d4];
        #pragma unroll
        for (int k = 0; k < 4; k++) {
            float wv = Wh[(d4 + k) * EE + lane];
            #pragma unroll
            for (int r = 0; r < RPW; r++)
                acc[r] = fmaf((&xv[r].x)[k], wv, acc[r]);
        }
    }

    float* dst = half ? g_dstb : g_src;
    #pragma unroll
    for (int r = 0; r < RPW; r++)
        dst[(row0 + r0 + r) * EE + lane] = acc[r];
}

// ---------------------------------------------------------------------------
// Kernel 2: edge reduce, e-packed f32x2, 8 j's per thread, direct atomics.
// Grid (4,8,16) = 512 blocks, 256 threads, 24 KB smem.
// ---------------------------------------------------------------------------
__global__ __launch_bounds__(256) void edge_reduce_kernel(
    const float* __restrict__ Wr,
    float* __restrict__ out)
{
    const int jb = blockIdx.x;                  // 0..3
    const int b  = blockIdx.y;
    const int s  = blockIdx.z;
    const int tid  = threadIdx.x;
    const int lane = tid & 31;
    const int w    = tid >> 5;                  // warp 0..7
    const int le   = lane & 15;                 // e-pair index (e = 2*le)
    const int jg   = lane >> 4;                 // j-group within warp (0/1)

    __shared__ float4 q_sh [IT * 16];           // 8 KB: (s0,s1,w0,w1) quads
    __shared__ float  dst_sh[JT * EE];          // 16 KB

    // stage: dst (4 float4/thread); src+Wr interleaved into quads (1/thread)
    {
        const float4* dst_g = (const float4*)(g_dstb + (b * NN + jb * JT) * EE);
        const float4* src_g = (const float4*)(g_src  + (b * NN + s  * IT) * EE);
        const float4* wr_g  = (const float4*)(Wr + s * IT * EE);
        #pragma unroll
        for (int k = 0; k < 4; k++)
            ((float4*)dst_sh)[k * 256 + tid] = dst_g[k * 256 + tid];

        float4 sv = src_g[tid];                 // 256 float4 = IT*EE/4
        float4 wv = wr_g [tid];
        const int row = tid >> 3, c8 = tid & 7;
        q_sh[row * 16 + c8 * 2    ] = make_float4(sv.x, sv.y, wv.x, wv.y);
        q_sh[row * 16 + c8 * 2 + 1] = make_float4(sv.z, sv.w, wv.z, wv.w);
    }
    __syncthreads();

    const int jl0 = w * 16 + jg * JR;           // this thread's first j (of 8)
    F2U dreg2[JR], acc2[JR];
    #pragma unroll
    for (int r = 0; r < JR; r++) {
        dreg2[r].f = *(const float2*)&dst_sh[(jl0 + r) * EE + 2 * le];
        acc2[r].u  = 0ull;
    }

    // inner loop: 1 LDS.128 + 32 pipe issues per i, covering 256 element-ops
    float4 cur = q_sh[le];
    #pragma unroll 4
    for (int i = 0; i < IT; i++) {
        const float4 nxt = (i + 1 < IT) ? q_sh[(i + 1) * 16 + le] : cur;
        F2U sv2, wv2;
        sv2.f.x = cur.x; sv2.f.y = cur.y;
        wv2.f.x = cur.z; wv2.f.y = cur.w;
        #pragma unroll
        for (int r = 0; r < JR; r++) {
            F2U t; t.u = add2(sv2.u, dreg2[r].u);       // FADD2
            t.f.x = fmaxf(t.f.x, 0.0f);                 // FMNMX (alu pipe)
            t.f.y = fmaxf(t.f.y, 0.0f);
            acc2[r].u = fma2(t.u, wv2.u, acc2[r].u);    // FFMA2
        }
        cur = nxt;
    }

    // collapse e-pair, reduce over the 16 lanes of each half-warp
    float acc[JR];
    #pragma unroll
    for (int r = 0; r < JR; r++) {
        acc[r] = acc2[r].f.x + acc2[r].f.y;
        #pragma unroll
        for (int off = 8; off; off >>= 1)
            acc[r] += __shfl_xor_sync(0xFFFFFFFFu, acc[r], off);
    }

    if (le == 0) {                              // lanes 0 and 16: 8 atomics each
        const int j = jb * JT + jl0;
        #pragma unroll
        for (int r = 0; r < JR; r++)
            atomicAdd(&out[b * NN + j + r], acc[r]);
    }
}

// ---------------------------------------------------------------------------
// launch: TWO kernels, direct-atomic output (R14 structure)
// ---------------------------------------------------------------------------
extern "C" void kernel_launch(void* const* d_in, const int* in_sizes, int n_in,
                              void* d_out, int out_size)
{
    const float* x  = (const float*)d_in[0];   // (8,512,64)
    const float* We = (const float*)d_in[1];   // (128,32)
    const float* be = (const float*)d_in[2];   // (32,)
    const float* Wr = (const float*)d_in[3];   // (16384,1)
    const float* br = (const float*)d_in[4];   // (1,)
    float* out = (float*)d_out;                // (8,512,1)

    proj_kernel<<<BB * NN / RPB, 256>>>(x, We, be, br, out);

    dim3 grid(NN / JT, BB, SS);                // (4,8,16) = 512 blocks
    edge_reduce_kernel<<<grid, 256>>>(Wr, out);
}

// round 17
// speedup vs baseline: 1.0208x; 1.0208x over previous
#include <cuda_runtime.h>
#include <cuda_bf16.h>

// Problem constants
#define BB 8
#define NN 512
#define DD 64
#define EE 32

#define JT 64                 // edge: j's per block (8 warps x 8 j)
#define JR 4                  // edge: j's per thread
#define SS 16                 // i-splits
#define IT (NN / SS)          // 32 i-rows per block

#define RPB 16                // proj: x-rows per block
#define RPW 4                 // proj: rows per warp

// Scratch (allocation-free rule -> __device__ globals)
__device__ float g_src [BB * NN * EE];        // src[b,n,e]
__device__ float g_dstb[BB * NN * EE];        // dst[b,n,e] + be[e]

// ---- packed fp32 pair helpers (sm_103a FADD2/FFMA2 via PTX f32x2) ----------
union F2U { unsigned long long u; float2 f; };

__device__ __forceinline__ unsigned long long add2(unsigned long long a,
                                                   unsigned long long b) {
    unsigned long long r;
    asm("add.rn.f32x2 %0, %1, %2;" : "=l"(r) : "l"(a), "l"(b));
    return r;
}
__device__ __forceinline__ unsigned long long fma2(unsigned long long a,
                                                   unsigned long long b,
                                                   unsigned long long c) {
    unsigned long long r;
    asm("fma.rn.f32x2 %0, %1, %2, %3;" : "=l"(r) : "l"(a), "l"(b), "l"(c));
    return r;
}

// ---------------------------------------------------------------------------
// Kernel 1 (R14 exact): src = x @ We[:D], dstb = x @ We[D:] + be
// Blocks 0..15 also initialize out[] = br (stream order protects this).
// ---------------------------------------------------------------------------
__global__ __launch_bounds__(256) void proj_kernel(
    const float* __restrict__ x,
    const float* __restrict__ We,
    const float* __restrict__ be,
    const float* __restrict__ br,
    float* __restrict__ out)
{
    const int row0 = blockIdx.x * RPB;
    __shared__ float xs [RPB][DD];              // 4 KB
    __shared__ float Wsh[2 * DD][EE];           // 16 KB

    const int tid = threadIdx.x;

    if (blockIdx.x < 16)                        // out init: 16*256 = 4096
        out[blockIdx.x * 256 + tid] = br[0];

    #pragma unroll
    for (int k = 0; k < 4; k++)
        ((float4*)Wsh)[k * 256 + tid] = ((const float4*)We)[k * 256 + tid];
    ((float4*)xs)[tid] = ((const float4*)(x + row0 * DD))[tid];
    __syncthreads();

    const int lane = tid & 31;                  // = e
    const int w    = tid >> 5;
    const int half = w >> 2;                    // 0 = src, 1 = dst
    const int r0   = (w & 3) * RPW;

    const float* Wh = &Wsh[half * DD][0];
    const float bias = half ? be[lane] : 0.0f;

    float acc[RPW];
    #pragma unroll
    for (int r = 0; r < RPW; r++) acc[r] = bias;

    #pragma unroll
    for (int d4 = 0; d4 < DD; d4 += 4) {
        float4 xv[RPW];
        #pragma unroll
        for (int r = 0; r < RPW; r++)
            xv[r] = *(const float4*)&xs[r0 + r][d4];
        #pragma unroll
        for (int k = 0; k < 4; k++) {
            float wv = Wh[(d4 + k) * EE + lane];
            #pragma unroll
            for (int r = 0; r < RPW; r++)
                acc[r] = fmaf((&xv[r].x)[k], wv, acc[r]);
        }
    }

    float* dst = half ? g_dstb : g_src;
    #pragma unroll
    for (int r = 0; r < RPW; r++)
        dst[(row0 + r0 + r) * EE + lane] = acc[r];
}

// ---------------------------------------------------------------------------
// Kernel 2: edge reduce, e-packed f32x2, quad smem; dreg loaded DIRECTLY from
// global (coalesced LDG.64, issued before staging) — no dst_sh round-trip.
// Grid (8,8,16) = 1024 blocks, 256 threads, 8 KB smem.
// ---------------------------------------------------------------------------
__global__ __launch_bounds__(256) void edge_reduce_kernel(
    const float* __restrict__ Wr,
    float* __restrict__ out)
{
    const int jb = blockIdx.x;
    const int b  = blockIdx.y;
    const int s  = blockIdx.z;
    const int tid  = threadIdx.x;
    const int lane = tid & 31;
    const int w    = tid >> 5;                  // warp 0..7
    const int le   = lane & 15;                 // e-pair index (e = 2*le)
    const int jg   = lane >> 4;                 // j-group within warp (0/1)

    __shared__ float4 q_sh[IT * 16];            // 8 KB: (s0,s1,w0,w1) quads

    const int jl0 = w * 8 + jg * JR;            // this thread's first j (of 4)

    // dreg: direct coalesced LDG.64 (independent of smem, issued first so the
    // latency overlaps the q_sh staging below)
    F2U dreg2[JR], acc2[JR];
    {
        const float* dg = g_dstb + (b * NN + jb * JT + jl0) * EE + 2 * le;
        #pragma unroll
        for (int r = 0; r < JR; r++) {
            dreg2[r].f = *(const float2*)(dg + r * EE);  // 128B per half-warp
            acc2[r].u  = 0ull;
        }
    }

    // stage src+Wr interleaved into quads (1 float4 each per thread)
    {
        const float4* src_g = (const float4*)(g_src + (b * NN + s * IT) * EE);
        const float4* wr_g  = (const float4*)(Wr + s * IT * EE);
        float4 sv = src_g[tid];                 // 256 float4 = IT*EE/4
        float4 wv = wr_g [tid];
        const int row = tid >> 3, c8 = tid & 7;
        q_sh[row * 16 + c8 * 2    ] = make_float4(sv.x, sv.y, wv.x, wv.y);
        q_sh[row * 16 + c8 * 2 + 1] = make_float4(sv.z, sv.w, wv.z, wv.w);
    }
    __syncthreads();

    // inner loop: 1 LDS.128 + 16 pipe issues per i (double-buffered)
    float4 cur = q_sh[le];
    #pragma unroll 4
    for (int i = 0; i < IT; i++) {
        const float4 nxt = (i + 1 < IT) ? q_sh[(i + 1) * 16 + le] : cur;
        F2U sv2, wv2;
        sv2.f.x = cur.x; sv2.f.y = cur.y;
        wv2.f.x = cur.z; wv2.f.y = cur.w;
        #pragma unroll
        for (int r = 0; r < JR; r++) {
            F2U t; t.u = add2(sv2.u, dreg2[r].u);       // FADD2
            t.f.x = fmaxf(t.f.x, 0.0f);                 // FMNMX (alu pipe)
            t.f.y = fmaxf(t.f.y, 0.0f);
            acc2[r].u = fma2(t.u, wv2.u, acc2[r].u);    // FFMA2
        }
        cur = nxt;
    }

    // collapse e-pair, reduce over the 16 lanes of each half-warp
    float acc[JR];
    #pragma unroll
    for (int r = 0; r < JR; r++) {
        acc[r] = acc2[r].f.x + acc2[r].f.y;
        #pragma unroll
        for (int off = 8; off; off >>= 1)
            acc[r] += __shfl_xor_sync(0xFFFFFFFFu, acc[r], off);
    }

    if (le == 0) {                              // lanes 0 and 16: 4 atomics each
        const int j = jb * JT + jl0;
        #pragma unroll
        for (int r = 0; r < JR; r++)
            atomicAdd(&out[b * NN + j + r], acc[r]);
    }
}

// ---------------------------------------------------------------------------
// launch: TWO kernels, direct-atomic output (R14 structure)
// ---------------------------------------------------------------------------
extern "C" void kernel_launch(void* const* d_in, const int* in_sizes, int n_in,
                              void* d_out, int out_size)
{
    const float* x  = (const float*)d_in[0];   // (8,512,64)
    const float* We = (const float*)d_in[1];   // (128,32)
    const float* be = (const float*)d_in[2];   // (32,)
    const float* Wr = (const float*)d_in[3];   // (16384,1)
    const float* br = (const float*)d_in[4];   // (1,)
    float* out = (float*)d_out;                // (8,512,1)

    proj_kernel<<<BB * NN / RPB, 256>>>(x, We, be, br, out);

    dim3 grid(NN / JT, BB, SS);                // (8,8,16) = 1024 blocks
    edge_reduce_kernel<<<grid, 256>>>(Wr, out);
}